// round 1
// baseline (speedup 1.0000x reference)
#include <cuda_runtime.h>

#define NB 4096
#define NT 168
#define NH 128
#define NG 512
#define NO 24

// ------------------------- device scratch -------------------------
__device__ float g_enc[NB * NT * NH];   // encoder hidden states (B,T,H)
__device__ float g_Ue [NB * NT * NH];   // Ua @ enc_outs        (B,T,H)
__device__ float g_h  [NB * NH];
__device__ float g_c  [NB * NH];
__device__ float g_ctx[NB * NH];
__device__ float g_pred[NB];
__device__ float g_WencT[NH * NG];      // enc_Whh transposed: [k][g]
__device__ float g_UaT [NH * NH];       // Ua transposed:      [k][u]
__device__ float g_WaT [NH * NH];       // Wa transposed:      [k][u]
__device__ float g_WdT [2 * NH * NG];   // [ctx|h]-major decoder weights: [k][g]
__device__ float g_encB[NG];
__device__ float g_decB[NG];

__device__ __forceinline__ float fsig(float x)   { return __fdividef(1.f, 1.f + __expf(-x)); }
__device__ __forceinline__ float ftanh_(float x) { return 1.f - __fdividef(2.f, 1.f + __expf(2.f * x)); }

// ------------------------- weight packing -------------------------
__global__ void pack_kernel(const float* __restrict__ encWhh,
                            const float* __restrict__ encBih, const float* __restrict__ encBhh,
                            const float* __restrict__ Wa, const float* __restrict__ Ua,
                            const float* __restrict__ decWih, const float* __restrict__ decWhh,
                            const float* __restrict__ decBih, const float* __restrict__ decBhh)
{
    int stride = gridDim.x * blockDim.x;
    int i0 = blockIdx.x * blockDim.x + threadIdx.x;
    for (int i = i0; i < NH * NG; i += stride) {
        int k = i / NG, g = i % NG;
        g_WencT[i] = encWhh[g * NH + k];
    }
    for (int i = i0; i < NH * NH; i += stride) {
        int k = i / NH, u = i % NH;
        g_UaT[i] = Ua[u * NH + k];
        g_WaT[i] = Wa[u * NH + k];
    }
    for (int i = i0; i < 2 * NH * NG; i += stride) {
        int k = i / NG, g = i % NG;
        g_WdT[i] = (k < NH) ? decWih[g * (NH + 1) + 1 + k] : decWhh[g * NH + (k - NH)];
    }
    for (int i = i0; i < NG; i += stride) {
        g_encB[i] = encBih[i] + encBhh[i];
        g_decB[i] = decBih[i] + decBhh[i];
    }
}

// ------------------------- encoder (one launch, 168 steps inside) -------------------------
// block: 256 threads, 16 batch rows. thread = (unit u, row-half rh) -> owns all 4 gates
// of unit u for its 8 rows. h lives in smem [row][k]; weights k-major from L1/L2.
__global__ void __launch_bounds__(256) enc_kernel(const float* __restrict__ x,
                                                  const float* __restrict__ encWih)
{
    __shared__ float hsh[16][NH];
    int tid = threadIdx.x;
    int u = tid & 127, rh = tid >> 7;
    int r0 = rh * 8;
    int b0 = blockIdx.x * 16;

    float wih[4], bs[4];
    #pragma unroll
    for (int j = 0; j < 4; j++) { wih[j] = encWih[u + 128 * j]; bs[j] = g_encB[u + 128 * j]; }

    float c[8];
    #pragma unroll
    for (int r = 0; r < 8; r++) c[r] = 0.f;

    for (int i = tid; i < 16 * NH; i += 256) ((float*)hsh)[i] = 0.f;
    __syncthreads();

    for (int t = 0; t < NT; t++) {
        float acc[4][8];
        #pragma unroll
        for (int r = 0; r < 8; r++) {
            float xv = x[(b0 + r0 + r) * NT + t];
            #pragma unroll
            for (int j = 0; j < 4; j++) acc[j][r] = xv * wih[j] + bs[j];
        }
        #pragma unroll 2
        for (int k = 0; k < NH; k++) {
            float w0 = g_WencT[k * NG + u];
            float w1 = g_WencT[k * NG + u + 128];
            float w2 = g_WencT[k * NG + u + 256];
            float w3 = g_WencT[k * NG + u + 384];
            #pragma unroll
            for (int r = 0; r < 8; r++) {
                float hv = hsh[r0 + r][k];
                acc[0][r] += w0 * hv; acc[1][r] += w1 * hv;
                acc[2][r] += w2 * hv; acc[3][r] += w3 * hv;
            }
        }
        __syncthreads();
        #pragma unroll
        for (int r = 0; r < 8; r++) {
            float iv = fsig(acc[0][r]), fv = fsig(acc[1][r]);
            float gv = ftanh_(acc[2][r]), ov = fsig(acc[3][r]);
            c[r] = fv * c[r] + iv * gv;
            float hv = ov * ftanh_(c[r]);
            hsh[r0 + r][u] = hv;
            g_enc[(b0 + r0 + r) * (NT * NH) + t * NH + u] = hv;
        }
        __syncthreads();
    }
    #pragma unroll
    for (int r = 0; r < 8; r++) {
        g_h[(b0 + r0 + r) * NH + u] = hsh[r0 + r][u];
        g_c[(b0 + r0 + r) * NH + u] = c[r];
    }
}

// ------------------------- Ue = enc_outs @ Ua^T -------------------------
// block: 256 threads, 32 (b,t)-rows staged in smem.
__global__ void __launch_bounds__(256) ue_kernel()
{
    __shared__ float esh[32][NH];
    int tid = threadIdx.x;
    int row0 = blockIdx.x * 32;
    for (int i = tid; i < 32 * NH; i += 256) esh[i >> 7][i & 127] = g_enc[row0 * NH + i];
    __syncthreads();
    int u = tid & 127, rh = tid >> 7;
    float acc[16];
    #pragma unroll
    for (int r = 0; r < 16; r++) acc[r] = 0.f;
    #pragma unroll 2
    for (int k = 0; k < NH; k++) {
        float w = g_UaT[k * NH + u];
        #pragma unroll
        for (int r = 0; r < 16; r++) acc[r] += w * esh[rh * 16 + r][k];
    }
    #pragma unroll
    for (int r = 0; r < 16; r++) g_Ue[(row0 + rh * 16 + r) * NH + u] = acc[r];
}

// ------------------------- decoder attention (per step) -------------------------
// block: 256 threads, 8 rows; warp per row for score/softmax/context.
__global__ void __launch_bounds__(256) att_kernel(const float* __restrict__ va)
{
    __shared__ float hsh[8][NH];
    __shared__ float qsh[8][NH];
    __shared__ float ssh[8][NT];
    int tid = threadIdx.x;
    int b0 = blockIdx.x * 8;
    for (int i = tid; i < 8 * NH; i += 256) hsh[i >> 7][i & 127] = g_h[b0 * NH + i];
    __syncthreads();

    // q = h @ Wa^T
    {
        int u = tid & 127, rh = tid >> 7;
        float qa[4] = {0.f, 0.f, 0.f, 0.f};
        #pragma unroll 2
        for (int k = 0; k < NH; k++) {
            float w = g_WaT[k * NH + u];
            #pragma unroll
            for (int r = 0; r < 4; r++) qa[r] += w * hsh[rh * 4 + r][k];
        }
        #pragma unroll
        for (int r = 0; r < 4; r++) qsh[rh * 4 + r][u] = qa[r];
    }
    __syncthreads();

    int wid = tid >> 5, lane = tid & 31;
    int b = b0 + wid;
    float4 q4 = *(float4*)&qsh[wid][lane * 4];
    float4 v4;
    v4.x = va[lane * 4]; v4.y = va[lane * 4 + 1]; v4.z = va[lane * 4 + 2]; v4.w = va[lane * 4 + 3];

    const float* uer = g_Ue + b * (NT * NH);
    float m = -1e30f;
    for (int t = 0; t < NT; t++) {
        float4 ue = *(const float4*)(uer + t * NH + lane * 4);
        float s = ftanh_(ue.x + q4.x) * v4.x + ftanh_(ue.y + q4.y) * v4.y
                + ftanh_(ue.z + q4.z) * v4.z + ftanh_(ue.w + q4.w) * v4.w;
        #pragma unroll
        for (int off = 16; off > 0; off >>= 1) s += __shfl_xor_sync(0xffffffffu, s, off);
        if (lane == 0) ssh[wid][t] = s;
        m = fmaxf(m, s);
    }
    __syncwarp();
    float Z = 0.f;
    for (int t = lane; t < NT; t += 32) {
        float w = __expf(ssh[wid][t] - m);
        ssh[wid][t] = w;
        Z += w;
    }
    #pragma unroll
    for (int off = 16; off > 0; off >>= 1) Z += __shfl_xor_sync(0xffffffffu, Z, off);
    float invZ = __fdividef(1.f, Z);
    __syncwarp();

    const float* er = g_enc + b * (NT * NH);
    float4 ca = {0.f, 0.f, 0.f, 0.f};
    for (int t = 0; t < NT; t++) {
        float w = ssh[wid][t];
        float4 e = *(const float4*)(er + t * NH + lane * 4);
        ca.x += w * e.x; ca.y += w * e.y; ca.z += w * e.z; ca.w += w * e.w;
    }
    ca.x *= invZ; ca.y *= invZ; ca.z *= invZ; ca.w *= invZ;
    *(float4*)&g_ctx[b * NH + lane * 4] = ca;
}

// ------------------------- decoder LSTM cell + fc (per step) -------------------------
// block: 256 threads, 16 rows. Same (u, row-half) microkernel as encoder, K=257.
__global__ void __launch_bounds__(256) cell_kernel(const float* __restrict__ x,
                                                   const float* __restrict__ decWih,
                                                   const float* __restrict__ fcW,
                                                   const float* __restrict__ fcb,
                                                   float* __restrict__ out, int step)
{
    __shared__ float ch[16][2 * NH];   // [row][ ctx(128) | h(128) ]
    __shared__ float din[16];
    int tid = threadIdx.x;
    int b0 = blockIdx.x * 16;
    for (int i = tid; i < 16 * NH; i += 256) {
        int r = i >> 7, k = i & 127;
        ch[r][k]      = g_ctx[(b0 + r) * NH + k];
        ch[r][NH + k] = g_h  [(b0 + r) * NH + k];
    }
    if (tid < 16) din[tid] = (step == 0) ? x[(b0 + tid) * NT + (NT - 1)] : g_pred[b0 + tid];
    __syncthreads();

    int u = tid & 127, rh = tid >> 7;
    float w0[4], bs[4];
    #pragma unroll
    for (int j = 0; j < 4; j++) {
        w0[j] = decWih[(u + 128 * j) * (NH + 1)];
        bs[j] = g_decB[u + 128 * j];
    }
    float acc[4][8];
    #pragma unroll
    for (int r = 0; r < 8; r++) {
        float dv = din[rh * 8 + r];
        #pragma unroll
        for (int j = 0; j < 4; j++) acc[j][r] = dv * w0[j] + bs[j];
    }
    #pragma unroll 2
    for (int k = 0; k < 2 * NH; k++) {
        float w0_ = g_WdT[k * NG + u];
        float w1_ = g_WdT[k * NG + u + 128];
        float w2_ = g_WdT[k * NG + u + 256];
        float w3_ = g_WdT[k * NG + u + 384];
        #pragma unroll
        for (int r = 0; r < 8; r++) {
            float hv = ch[rh * 8 + r][k];
            acc[0][r] += w0_ * hv; acc[1][r] += w1_ * hv;
            acc[2][r] += w2_ * hv; acc[3][r] += w3_ * hv;
        }
    }
    float hnew[8];
    #pragma unroll
    for (int r = 0; r < 8; r++) {
        int b = b0 + rh * 8 + r;
        float cold = g_c[b * NH + u];
        float iv = fsig(acc[0][r]), fv = fsig(acc[1][r]);
        float gv = ftanh_(acc[2][r]), ov = fsig(acc[3][r]);
        float cn = fv * cold + iv * gv;
        float hn = ov * ftanh_(cn);
        g_c[b * NH + u] = cn;
        g_h[b * NH + u] = hn;
        hnew[r] = hn;
    }
    __syncthreads();   // all k-loop smem reads complete before overwrite
    #pragma unroll
    for (int r = 0; r < 8; r++) ch[rh * 8 + r][u] = hnew[r];
    __syncthreads();

    // pred = h2 @ fcW^T + fcb ; warp handles 2 rows
    int wid = tid >> 5, lane = tid & 31;
    float fw0 = fcW[lane], fw1 = fcW[lane + 32], fw2 = fcW[lane + 64], fw3 = fcW[lane + 96];
    #pragma unroll
    for (int rr = 0; rr < 2; rr++) {
        int r = wid * 2 + rr;
        float s = ch[r][lane] * fw0 + ch[r][lane + 32] * fw1
                + ch[r][lane + 64] * fw2 + ch[r][lane + 96] * fw3;
        #pragma unroll
        for (int off = 16; off > 0; off >>= 1) s += __shfl_xor_sync(0xffffffffu, s, off);
        if (lane == 0) {
            float p = s + fcb[0];
            out[(b0 + r) * NO + step] = p;
            g_pred[b0 + r] = p;
        }
    }
}

// ------------------------- launch -------------------------
extern "C" void kernel_launch(void* const* d_in, const int* in_sizes, int n_in,
                              void* d_out, int out_size)
{
    const float* x      = (const float*)d_in[0];
    const float* encWih = (const float*)d_in[1];
    const float* encWhh = (const float*)d_in[2];
    const float* encBih = (const float*)d_in[3];
    const float* encBhh = (const float*)d_in[4];
    const float* Wa     = (const float*)d_in[5];
    const float* Ua     = (const float*)d_in[6];
    const float* va     = (const float*)d_in[7];
    const float* decWih = (const float*)d_in[8];
    const float* decWhh = (const float*)d_in[9];
    const float* decBih = (const float*)d_in[10];
    const float* decBhh = (const float*)d_in[11];
    const float* fcW    = (const float*)d_in[12];
    const float* fcb    = (const float*)d_in[13];
    float* out = (float*)d_out;

    pack_kernel<<<128, 256>>>(encWhh, encBih, encBhh, Wa, Ua, decWih, decWhh, decBih, decBhh);
    enc_kernel<<<NB / 16, 256>>>(x, encWih);
    ue_kernel<<<NB * NT / 32, 256>>>();
    for (int d = 0; d < NO; d++) {
        att_kernel<<<NB / 8, 256>>>(va);
        cell_kernel<<<NB / 16, 256>>>(x, decWih, fcW, fcb, out, d);
    }
}

// round 2
// speedup vs baseline: 1.0068x; 1.0068x over previous
#include <cuda_runtime.h>
#include <cuda_fp16.h>

#define NB 4096
#define NT 168
#define NH 128
#define NG 512
#define NO 24

// ------------------------- device scratch -------------------------
__device__ __half g_ench[NB * NT * NH];  // encoder hidden states (B,T,H) fp16
__device__ __half g_Ueh [NB * NT * NH];  // Ua @ enc_outs        (B,T,H) fp16
__device__ float g_h  [NB * NH];
__device__ float g_c  [NB * NH];
__device__ float g_ctx[NB * NH];
__device__ float g_pred[NB];
__device__ float g_WencT[NH * NG];      // enc_Whh transposed: [k][g]
__device__ float g_UaT [NH * NH];       // Ua transposed:      [k][u]
__device__ float g_WaT [NH * NH];       // Wa transposed:      [k][u]
__device__ float g_WdT [2 * NH * NG];   // [ctx|h]-major decoder weights: [k][g]
__device__ float g_encB[NG];
__device__ float g_decB[NG];

// accurate activations (recurrent paths)
__device__ __forceinline__ float fsig(float x)   { return __fdividef(1.f, 1.f + __expf(-x)); }
__device__ __forceinline__ float ftanh_(float x) { return 1.f - __fdividef(2.f, 1.f + __expf(2.f * x)); }
// fast tanh (attention energy only, non-recurrent)
__device__ __forceinline__ float ftanh_fast(float x) { asm("tanh.approx.f32 %0, %0;" : "+f"(x)); return x; }

// ------------------------- weight packing -------------------------
__global__ void pack_kernel(const float* __restrict__ encWhh,
                            const float* __restrict__ encBih, const float* __restrict__ encBhh,
                            const float* __restrict__ Wa, const float* __restrict__ Ua,
                            const float* __restrict__ decWih, const float* __restrict__ decWhh,
                            const float* __restrict__ decBih, const float* __restrict__ decBhh)
{
    int stride = gridDim.x * blockDim.x;
    int i0 = blockIdx.x * blockDim.x + threadIdx.x;
    for (int i = i0; i < NH * NG; i += stride) {
        int k = i / NG, g = i % NG;
        g_WencT[i] = encWhh[g * NH + k];
    }
    for (int i = i0; i < NH * NH; i += stride) {
        int k = i / NH, u = i % NH;
        g_UaT[i] = Ua[u * NH + k];
        g_WaT[i] = Wa[u * NH + k];
    }
    for (int i = i0; i < 2 * NH * NG; i += stride) {
        int k = i / NG, g = i % NG;
        g_WdT[i] = (k < NH) ? decWih[g * (NH + 1) + 1 + k] : decWhh[g * NH + (k - NH)];
    }
    for (int i = i0; i < NG; i += stride) {
        g_encB[i] = encBih[i] + encBhh[i];
        g_decB[i] = decBih[i] + decBhh[i];
    }
}

// ------------------------- encoder (one launch, 168 steps inside) -------------------------
__global__ void __launch_bounds__(256) enc_kernel(const float* __restrict__ x,
                                                  const float* __restrict__ encWih)
{
    __shared__ float hsh[16][NH];
    int tid = threadIdx.x;
    int u = tid & 127, rh = tid >> 7;
    int r0 = rh * 8;
    int b0 = blockIdx.x * 16;

    float wih[4], bs[4];
    #pragma unroll
    for (int j = 0; j < 4; j++) { wih[j] = encWih[u + 128 * j]; bs[j] = g_encB[u + 128 * j]; }

    float c[8];
    #pragma unroll
    for (int r = 0; r < 8; r++) c[r] = 0.f;

    for (int i = tid; i < 16 * NH; i += 256) ((float*)hsh)[i] = 0.f;
    __syncthreads();

    for (int t = 0; t < NT; t++) {
        float acc[4][8];
        #pragma unroll
        for (int r = 0; r < 8; r++) {
            float xv = x[(b0 + r0 + r) * NT + t];
            #pragma unroll
            for (int j = 0; j < 4; j++) acc[j][r] = xv * wih[j] + bs[j];
        }
        #pragma unroll 2
        for (int k = 0; k < NH; k++) {
            float w0 = g_WencT[k * NG + u];
            float w1 = g_WencT[k * NG + u + 128];
            float w2 = g_WencT[k * NG + u + 256];
            float w3 = g_WencT[k * NG + u + 384];
            #pragma unroll
            for (int r = 0; r < 8; r++) {
                float hv = hsh[r0 + r][k];
                acc[0][r] += w0 * hv; acc[1][r] += w1 * hv;
                acc[2][r] += w2 * hv; acc[3][r] += w3 * hv;
            }
        }
        __syncthreads();
        #pragma unroll
        for (int r = 0; r < 8; r++) {
            float iv = fsig(acc[0][r]), fv = fsig(acc[1][r]);
            float gv = ftanh_(acc[2][r]), ov = fsig(acc[3][r]);
            c[r] = fv * c[r] + iv * gv;
            float hv = ov * ftanh_(c[r]);
            hsh[r0 + r][u] = hv;
            g_ench[(size_t)(b0 + r0 + r) * (NT * NH) + t * NH + u] = __float2half_rn(hv);
        }
        __syncthreads();
    }
    #pragma unroll
    for (int r = 0; r < 8; r++) {
        g_h[(b0 + r0 + r) * NH + u] = hsh[r0 + r][u];
        g_c[(b0 + r0 + r) * NH + u] = c[r];
    }
}

// ------------------------- Ue = enc_outs @ Ua^T -------------------------
// block: 256 threads = 8 warps; warp handles 4 rows; lane handles 4 units.
// per k: 1 LDG.128 (weights) + 4 LDS broadcast + 16 FFMA.
__global__ void __launch_bounds__(256) ue_kernel()
{
    __shared__ float esh[32][NH];
    int tid = threadIdx.x;
    size_t row0 = (size_t)blockIdx.x * 32;
    // stage 32 rows fp16 -> fp32 smem (vectorized half2)
    const __half2* src = (const __half2*)(g_ench + row0 * NH);
    for (int i = tid; i < 32 * NH / 2; i += 256) {
        float2 f = __half22float2(src[i]);
        int r = i >> 6, k = (i & 63) * 2;
        esh[r][k] = f.x; esh[r][k + 1] = f.y;
    }
    __syncthreads();

    int lane = tid & 31, wid = tid >> 5;
    int u4 = lane * 4, r0 = wid * 4;
    float acc[4][4];
    #pragma unroll
    for (int r = 0; r < 4; r++)
        #pragma unroll
        for (int j = 0; j < 4; j++) acc[r][j] = 0.f;

    #pragma unroll 4
    for (int k = 0; k < NH; k++) {
        float4 w = *(const float4*)&g_UaT[k * NH + u4];
        #pragma unroll
        for (int r = 0; r < 4; r++) {
            float e = esh[r0 + r][k];
            acc[r][0] += w.x * e; acc[r][1] += w.y * e;
            acc[r][2] += w.z * e; acc[r][3] += w.w * e;
        }
    }
    #pragma unroll
    for (int r = 0; r < 4; r++) {
        __half2* orow = (__half2*)(g_Ueh + (row0 + r0 + r) * NH);
        orow[lane * 2]     = __floats2half2_rn(acc[r][0], acc[r][1]);
        orow[lane * 2 + 1] = __floats2half2_rn(acc[r][2], acc[r][3]);
    }
}

// ------------------------- decoder attention (per step) -------------------------
// block: 128 threads, 4 rows; warp per row. fp16 streams, tanh.approx energy.
__global__ void __launch_bounds__(128) att_kernel(const float* __restrict__ va)
{
    __shared__ float hsh[4][NH];
    __shared__ float qsh[4][NH];
    __shared__ float ssh[4][NT];
    int tid = threadIdx.x;
    int b0 = blockIdx.x * 4;
    for (int i = tid; i < 4 * NH; i += 128) hsh[i >> 7][i & 127] = g_h[b0 * NH + i];
    __syncthreads();

    // q = h @ Wa^T  (128 threads = all units, 4 rows each)
    {
        int u = tid;
        float qa[4] = {0.f, 0.f, 0.f, 0.f};
        #pragma unroll 4
        for (int k = 0; k < NH; k++) {
            float w = g_WaT[k * NH + u];
            #pragma unroll
            for (int r = 0; r < 4; r++) qa[r] += w * hsh[r][k];
        }
        #pragma unroll
        for (int r = 0; r < 4; r++) qsh[r][u] = qa[r];
    }
    __syncthreads();

    int wid = tid >> 5, lane = tid & 31;
    int b = b0 + wid;
    float4 q4 = *(float4*)&qsh[wid][lane * 4];
    float4 v4 = *(const float4*)&va[lane * 4];

    // scores: s_t = v . tanh(Ue_t + q)
    const uint2* uep = (const uint2*)(g_Ueh + (size_t)b * NT * NH);
    float m = -1e30f;
    for (int t0 = 0; t0 < NT; t0 += 4) {
        float s[4];
        #pragma unroll
        for (int j = 0; j < 4; j++) {
            uint2 raw = uep[(t0 + j) * 32 + lane];
            float2 f0 = __half22float2(*(__half2*)&raw.x);
            float2 f1 = __half22float2(*(__half2*)&raw.y);
            s[j] = ftanh_fast(f0.x + q4.x) * v4.x + ftanh_fast(f0.y + q4.y) * v4.y
                 + ftanh_fast(f1.x + q4.z) * v4.z + ftanh_fast(f1.y + q4.w) * v4.w;
        }
        #pragma unroll
        for (int j = 0; j < 4; j++) {
            #pragma unroll
            for (int o = 16; o > 0; o >>= 1) s[j] += __shfl_xor_sync(0xffffffffu, s[j], o);
            m = fmaxf(m, s[j]);
        }
        if (lane == 0) {
            ssh[wid][t0] = s[0]; ssh[wid][t0 + 1] = s[1];
            ssh[wid][t0 + 2] = s[2]; ssh[wid][t0 + 3] = s[3];
        }
    }
    __syncwarp();

    // softmax weights
    float Z = 0.f;
    for (int t = lane; t < NT; t += 32) {
        float w = __expf(ssh[wid][t] - m);
        ssh[wid][t] = w;
        Z += w;
    }
    #pragma unroll
    for (int o = 16; o > 0; o >>= 1) Z += __shfl_xor_sync(0xffffffffu, Z, o);
    float invZ = __fdividef(1.f, Z);
    __syncwarp();

    // context
    const uint2* ep = (const uint2*)(g_ench + (size_t)b * NT * NH);
    float4 ca = {0.f, 0.f, 0.f, 0.f};
    for (int t0 = 0; t0 < NT; t0 += 4) {
        #pragma unroll
        for (int j = 0; j < 4; j++) {
            float w = ssh[wid][t0 + j];
            uint2 raw = ep[(t0 + j) * 32 + lane];
            float2 f0 = __half22float2(*(__half2*)&raw.x);
            float2 f1 = __half22float2(*(__half2*)&raw.y);
            ca.x += w * f0.x; ca.y += w * f0.y;
            ca.z += w * f1.x; ca.w += w * f1.y;
        }
    }
    ca.x *= invZ; ca.y *= invZ; ca.z *= invZ; ca.w *= invZ;
    *(float4*)&g_ctx[b * NH + lane * 4] = ca;
}

// ------------------------- decoder LSTM cell + fc (per step) -------------------------
__global__ void __launch_bounds__(256) cell_kernel(const float* __restrict__ x,
                                                   const float* __restrict__ decWih,
                                                   const float* __restrict__ fcW,
                                                   const float* __restrict__ fcb,
                                                   float* __restrict__ out, int step)
{
    __shared__ float ch[16][2 * NH];   // [row][ ctx(128) | h(128) ]
    __shared__ float din[16];
    int tid = threadIdx.x;
    int b0 = blockIdx.x * 16;
    for (int i = tid; i < 16 * NH; i += 256) {
        int r = i >> 7, k = i & 127;
        ch[r][k]      = g_ctx[(b0 + r) * NH + k];
        ch[r][NH + k] = g_h  [(b0 + r) * NH + k];
    }
    if (tid < 16) din[tid] = (step == 0) ? x[(b0 + tid) * NT + (NT - 1)] : g_pred[b0 + tid];
    __syncthreads();

    int u = tid & 127, rh = tid >> 7;
    float w0[4], bs[4];
    #pragma unroll
    for (int j = 0; j < 4; j++) {
        w0[j] = decWih[(u + 128 * j) * (NH + 1)];
        bs[j] = g_decB[u + 128 * j];
    }
    float acc[4][8];
    #pragma unroll
    for (int r = 0; r < 8; r++) {
        float dv = din[rh * 8 + r];
        #pragma unroll
        for (int j = 0; j < 4; j++) acc[j][r] = dv * w0[j] + bs[j];
    }
    #pragma unroll 2
    for (int k = 0; k < 2 * NH; k++) {
        float w0_ = g_WdT[k * NG + u];
        float w1_ = g_WdT[k * NG + u + 128];
        float w2_ = g_WdT[k * NG + u + 256];
        float w3_ = g_WdT[k * NG + u + 384];
        #pragma unroll
        for (int r = 0; r < 8; r++) {
            float hv = ch[rh * 8 + r][k];
            acc[0][r] += w0_ * hv; acc[1][r] += w1_ * hv;
            acc[2][r] += w2_ * hv; acc[3][r] += w3_ * hv;
        }
    }
    float hnew[8];
    #pragma unroll
    for (int r = 0; r < 8; r++) {
        int b = b0 + rh * 8 + r;
        float cold = g_c[b * NH + u];
        float iv = fsig(acc[0][r]), fv = fsig(acc[1][r]);
        float gv = ftanh_(acc[2][r]), ov = fsig(acc[3][r]);
        float cn = fv * cold + iv * gv;
        float hn = ov * ftanh_(cn);
        g_c[b * NH + u] = cn;
        g_h[b * NH + u] = hn;
        hnew[r] = hn;
    }
    __syncthreads();
    #pragma unroll
    for (int r = 0; r < 8; r++) ch[rh * 8 + r][u] = hnew[r];
    __syncthreads();

    int wid = tid >> 5, lane = tid & 31;
    float fw0 = fcW[lane], fw1 = fcW[lane + 32], fw2 = fcW[lane + 64], fw3 = fcW[lane + 96];
    #pragma unroll
    for (int rr = 0; rr < 2; rr++) {
        int r = wid * 2 + rr;
        float s = ch[r][lane] * fw0 + ch[r][lane + 32] * fw1
                + ch[r][lane + 64] * fw2 + ch[r][lane + 96] * fw3;
        #pragma unroll
        for (int off = 16; off > 0; off >>= 1) s += __shfl_xor_sync(0xffffffffu, s, off);
        if (lane == 0) {
            float p = s + fcb[0];
            out[(b0 + r) * NO + step] = p;
            g_pred[b0 + r] = p;
        }
    }
}

// ------------------------- launch -------------------------
extern "C" void kernel_launch(void* const* d_in, const int* in_sizes, int n_in,
                              void* d_out, int out_size)
{
    const float* x      = (const float*)d_in[0];
    const float* encWih = (const float*)d_in[1];
    const float* encWhh = (const float*)d_in[2];
    const float* encBih = (const float*)d_in[3];
    const float* encBhh = (const float*)d_in[4];
    const float* Wa     = (const float*)d_in[5];
    const float* Ua     = (const float*)d_in[6];
    const float* va     = (const float*)d_in[7];
    const float* decWih = (const float*)d_in[8];
    const float* decWhh = (const float*)d_in[9];
    const float* decBih = (const float*)d_in[10];
    const float* decBhh = (const float*)d_in[11];
    const float* fcW    = (const float*)d_in[12];
    const float* fcb    = (const float*)d_in[13];
    float* out = (float*)d_out;

    pack_kernel<<<128, 256>>>(encWhh, encBih, encBhh, Wa, Ua, decWih, decWhh, decBih, decBhh);
    enc_kernel<<<NB / 16, 256>>>(x, encWih);
    ue_kernel<<<NB * NT / 32, 256>>>();
    for (int d = 0; d < NO; d++) {
        att_kernel<<<NB / 4, 128>>>(va);
        cell_kernel<<<NB / 16, 256>>>(x, decWih, fcW, fcb, out, d);
    }
}

// round 4
// speedup vs baseline: 2.2240x; 2.2089x over previous
#include <cuda_runtime.h>
#include <cuda_fp16.h>
#include <cstdint>

#define NB 4096
#define NT 168
#define NH 128
#define NG 512
#define NO 24

// ------------------------- device scratch -------------------------
__device__ __half g_ench[NB * NT * NH];  // encoder hidden states (B*T, H) fp16
__device__ __half g_Ueh [NB * NT * NH];  // Ua @ enc_outs        (B*T, H) fp16
__device__ float g_h  [NB * NH];
__device__ float g_c  [NB * NH];
__device__ float g_ctx[NB * NH];
__device__ float g_pred[NB];
__device__ __half g_WencP[8 * 8 * 8 * 32 * 4]; // enc weights in B-frag order [wid][kt][j][lane][4]
__device__ __half g_UaP  [16 * 8 * 32 * 4];    // Ua in B-frag order [nt][kt][lane][4]
__device__ float g_encBp[NG];           // enc bias, n = u*4+gate layout
__device__ float g_wihp [NG];           // enc Wih,  n = u*4+gate layout
__device__ float g_WaT [NH * NH];       // Wa transposed: [k][u]
__device__ float g_WdT [2 * NH * NG];   // [ctx|h]-major decoder weights: [k][g]
__device__ float g_decB[NG];

// accurate activations (recurrent paths)
__device__ __forceinline__ float fsig(float x)   { return __fdividef(1.f, 1.f + __expf(-x)); }
__device__ __forceinline__ float ftanh_(float x) { return 1.f - __fdividef(2.f, 1.f + __expf(2.f * x)); }
// fast tanh (attention energy only, non-recurrent)
__device__ __forceinline__ float ftanh_fast(float x) { asm("tanh.approx.f32 %0, %0;" : "+f"(x)); return x; }

// ------------------------- mma helpers -------------------------
__device__ __forceinline__ void ldmA(uint32_t a[4], const __half* p) {
    uint32_t addr = (uint32_t)__cvta_generic_to_shared(p);
    asm volatile("ldmatrix.sync.aligned.m8n8.x4.shared.b16 {%0,%1,%2,%3}, [%4];"
        : "=r"(a[0]), "=r"(a[1]), "=r"(a[2]), "=r"(a[3]) : "r"(addr));
}
__device__ __forceinline__ void mma16816(float c[4], const uint32_t a[4], uint2 b) {
    asm volatile("mma.sync.aligned.m16n8k16.row.col.f32.f16.f16.f32 "
        "{%0,%1,%2,%3},{%4,%5,%6,%7},{%8,%9},{%0,%1,%2,%3};"
        : "+f"(c[0]), "+f"(c[1]), "+f"(c[2]), "+f"(c[3])
        : "r"(a[0]), "r"(a[1]), "r"(a[2]), "r"(a[3]), "r"(b.x), "r"(b.y));
}

// ------------------------- weight packing -------------------------
__global__ void pack_kernel(const float* __restrict__ encWih,
                            const float* __restrict__ encWhh,
                            const float* __restrict__ encBih, const float* __restrict__ encBhh,
                            const float* __restrict__ Wa, const float* __restrict__ Ua,
                            const float* __restrict__ decWih, const float* __restrict__ decWhh,
                            const float* __restrict__ decBih, const float* __restrict__ decBhh)
{
    int stride = gridDim.x * blockDim.x;
    int i0 = blockIdx.x * blockDim.x + threadIdx.x;

    // enc Whh fragments: n = u*4 + gate
    for (int idx = i0; idx < 8 * 8 * 8 * 32 * 4; idx += stride) {
        int q = idx & 3, lane = (idx >> 2) & 31;
        int rest = idx >> 7;
        int j = rest & 7, kt = (rest >> 3) & 7, wid = rest >> 6;
        int g = lane >> 2, tg = lane & 3;
        int n = wid * 64 + j * 8 + g;
        int u = n >> 2, gate = n & 3;
        int k = kt * 16 + ((q < 2) ? (tg * 2 + q) : (tg * 2 + 8 + (q - 2)));
        g_WencP[idx] = __float2half_rn(encWhh[(gate * 128 + u) * NH + k]);
    }
    // Ua fragments: n = unit
    for (int idx = i0; idx < 16 * 8 * 32 * 4; idx += stride) {
        int q = idx & 3, lane = (idx >> 2) & 31;
        int rest = idx >> 7;
        int kt = rest & 7, nt = rest >> 3;
        int g = lane >> 2, tg = lane & 3;
        int n = nt * 8 + g;
        int k = kt * 16 + ((q < 2) ? (tg * 2 + q) : (tg * 2 + 8 + (q - 2)));
        g_UaP[idx] = __float2half_rn(Ua[n * NH + k]);
    }
    for (int i = i0; i < NH * NH; i += stride) {
        int k = i / NH, u = i % NH;
        g_WaT[i] = Wa[u * NH + k];
    }
    for (int i = i0; i < 2 * NH * NG; i += stride) {
        int k = i / NG, g = i % NG;
        g_WdT[i] = (k < NH) ? decWih[g * (NH + 1) + 1 + k] : decWhh[g * NH + (k - NH)];
    }
    for (int i = i0; i < NG; i += stride) {
        int u = i >> 2, gate = i & 3;
        g_encBp[i] = encBih[gate * 128 + u] + encBhh[gate * 128 + u];
        g_wihp[i]  = encWih[gate * 128 + u];
        g_decB[i] = decBih[i] + decBhh[i];
    }
}

// ------------------------- encoder (HMMA, one launch, 168 steps) -------------------------
// block: 256 thr = 8 warps, 32 batch rows (2 m-tiles). warp w covers gate-cols [w*64, w*64+64).
// h lives fp16 in smem; weights pre-packed B-frags from gmem (L1-resident).
__global__ void __launch_bounds__(256) enc_kernel(const float* __restrict__ x)
{
    __shared__ __half hsh[32][136];
    __shared__ float biassh[NG], wihsh[NG];
    int tid = threadIdx.x;
    int wid = tid >> 5, lane = tid & 31;
    int b0 = blockIdx.x * 32;
    int g = lane >> 2, tg = lane & 3, tg2 = tg >> 1;
    int odd = tg & 1;
    int lrow = lane & 15;
    int lcol = (lane >> 4) << 3;

    for (int i = tid; i < NG; i += 256) { biassh[i] = g_encBp[i]; wihsh[i] = g_wihp[i]; }
    for (int i = tid; i < 32 * 136; i += 256) ((__half*)hsh)[i] = __ushort_as_half(0);

    float cst[16];
    #pragma unroll
    for (int i = 0; i < 16; i++) cst[i] = 0.f;

    const uint2* wbase = ((const uint2*)g_WencP) + wid * 2048 + lane;
    __syncthreads();

    for (int t = 0; t < NT; t++) {
        // x scalars for this lane's two rows (issued early)
        float xv[2];
        #pragma unroll
        for (int mi = 0; mi < 2; mi++)
            xv[mi] = x[(b0 + mi * 16 + g + (odd ? 8 : 0)) * NT + t];

        float acc[2][8][4];
        #pragma unroll
        for (int mi = 0; mi < 2; mi++)
            #pragma unroll
            for (int j = 0; j < 8; j++)
                #pragma unroll
                for (int q = 0; q < 4; q++) acc[mi][j][q] = 0.f;

        #pragma unroll
        for (int kt = 0; kt < 8; kt++) {
            uint32_t a[2][4];
            #pragma unroll
            for (int mi = 0; mi < 2; mi++)
                ldmA(a[mi], &hsh[mi * 16 + lrow][kt * 16 + lcol]);
            #pragma unroll
            for (int j = 0; j < 8; j++) {
                uint2 b = wbase[(kt * 8 + j) * 32];
                mma16816(acc[0][j], a[0], b);
                mma16816(acc[1][j], a[1], b);
            }
        }
        __syncthreads();   // all mma reads of hsh done

        #pragma unroll
        for (int mi = 0; mi < 2; mi++) {
            int row = mi * 16 + g + (odd ? 8 : 0);
            #pragma unroll
            for (int j = 0; j < 8; j++) {
                float t0 = __shfl_xor_sync(0xffffffffu, acc[mi][j][0], 1);
                float t1 = __shfl_xor_sync(0xffffffffu, acc[mi][j][1], 1);
                float t2 = __shfl_xor_sync(0xffffffffu, acc[mi][j][2], 1);
                float t3 = __shfl_xor_sync(0xffffffffu, acc[mi][j][3], 1);
                float gi, gf, gg, go;
                if (!odd) { gi = acc[mi][j][0]; gf = acc[mi][j][1]; gg = t0; go = t1; }
                else      { gi = t2; gf = t3; gg = acc[mi][j][2]; go = acc[mi][j][3]; }
                int u = wid * 16 + j * 2 + tg2;
                float4 bi = *(const float4*)&biassh[u * 4];
                float4 wi = *(const float4*)&wihsh[u * 4];
                gi += bi.x + xv[mi] * wi.x;
                gf += bi.y + xv[mi] * wi.y;
                gg += bi.z + xv[mi] * wi.z;
                go += bi.w + xv[mi] * wi.w;
                float c = fsig(gf) * cst[mi * 8 + j] + fsig(gi) * ftanh_(gg);
                cst[mi * 8 + j] = c;
                float h = fsig(go) * ftanh_(c);
                hsh[row][u] = __float2half_rn(h);
            }
        }
        __syncthreads();   // hsh fully updated

        // coalesced copy of h_t to global fp16
        for (int i = tid; i < 512; i += 256) {
            int r = i >> 4, ch = i & 15;
            uint4 v = *(uint4*)&hsh[r][ch * 8];
            *(uint4*)&g_ench[(size_t)(b0 + r) * (NT * NH) + (size_t)t * NH + ch * 8] = v;
        }
    }
    __syncthreads();
    // final states for decoder
    for (int i = tid; i < 32 * NH; i += 256) {
        int r = i >> 7, u2 = i & 127;
        g_h[(b0 + r) * NH + u2] = __half2float(hsh[r][u2]);
    }
    #pragma unroll
    for (int mi = 0; mi < 2; mi++) {
        int row = mi * 16 + g + (odd ? 8 : 0);
        #pragma unroll
        for (int j = 0; j < 8; j++) {
            int u = wid * 16 + j * 2 + tg2;
            g_c[(b0 + row) * NH + u] = cst[mi * 8 + j];
        }
    }
}

// ------------------------- Ue = enc_outs @ Ua^T (HMMA) -------------------------
// block: 256 thr = 8 warps, 32 rows. warp = (mi, nw): m-tile mi, n-slice nw*32.
__global__ void __launch_bounds__(256) ue_kernel()
{
    __shared__ __half ash[32][136];
    int tid = threadIdx.x;
    int wid = tid >> 5, lane = tid & 31;
    size_t row0 = (size_t)blockIdx.x * 32;

    for (int i = tid; i < 512; i += 256) {
        int r = i >> 4, ch = i & 15;
        *(uint4*)&ash[r][ch * 8] = *(const uint4*)&g_ench[(row0 + r) * NH + ch * 8];
    }
    __syncthreads();

    int mi = wid & 1, nw = wid >> 1;
    int lrow = lane & 15, lcol = (lane >> 4) << 3;
    float acc[4][4];
    #pragma unroll
    for (int nt = 0; nt < 4; nt++)
        #pragma unroll
        for (int q = 0; q < 4; q++) acc[nt][q] = 0.f;

    const uint2* ub = (const uint2*)g_UaP;
    #pragma unroll
    for (int kt = 0; kt < 8; kt++) {
        uint32_t a[4];
        ldmA(a, &ash[mi * 16 + lrow][kt * 16 + lcol]);
        #pragma unroll
        for (int nt = 0; nt < 4; nt++) {
            int ntg = nw * 4 + nt;
            uint2 b = ub[(ntg * 8 + kt) * 32 + lane];
            mma16816(acc[nt], a, b);
        }
    }
    __syncthreads();   // ash reads done; reuse as output staging

    int g = lane >> 2, tg = lane & 3;
    #pragma unroll
    for (int nt = 0; nt < 4; nt++) {
        int n = (nw * 4 + nt) * 8 + tg * 2;
        *(__half2*)&ash[mi * 16 + g][n]     = __floats2half2_rn(acc[nt][0], acc[nt][1]);
        *(__half2*)&ash[mi * 16 + 8 + g][n] = __floats2half2_rn(acc[nt][2], acc[nt][3]);
    }
    __syncthreads();
    for (int i = tid; i < 512; i += 256) {
        int r = i >> 4, ch = i & 15;
        *(uint4*)&g_Ueh[(row0 + r) * NH + ch * 8] = *(uint4*)&ash[r][ch * 8];
    }
}

// ------------------------- decoder attention (per step) -------------------------
// block: 256 thr = 8 warps, 4 rows, 2 warps per row (split over T halves).
__global__ void __launch_bounds__(256) att_kernel(const float* __restrict__ va)
{
    __shared__ float hsh[4][NH];
    __shared__ float qsh[4][NH];
    __shared__ float ssh[4][NT];
    __shared__ float mred[4][2];
    __shared__ float zred[4][2];
    __shared__ float cpart[4][NH];
    int tid = threadIdx.x;
    int b0 = blockIdx.x * 4;
    for (int i = tid; i < 4 * NH; i += 256) hsh[i >> 7][i & 127] = g_h[b0 * NH + i];
    __syncthreads();

    // q = h @ Wa^T : 128 units x 2 row-pairs
    {
        int u = tid & 127, rh = tid >> 7;
        float qa0 = 0.f, qa1 = 0.f;
        #pragma unroll 4
        for (int k = 0; k < NH; k++) {
            float w = g_WaT[k * NH + u];
            qa0 += w * hsh[rh * 2][k];
            qa1 += w * hsh[rh * 2 + 1][k];
        }
        qsh[rh * 2][u] = qa0;
        qsh[rh * 2 + 1][u] = qa1;
    }
    __syncthreads();

    int wid = tid >> 5, lane = tid & 31;
    int row = wid >> 1, hf = wid & 1;
    int b = b0 + row;
    int tbeg = hf * 84;
    float4 q4 = *(float4*)&qsh[row][lane * 4];
    float4 v4 = *(const float4*)&va[lane * 4];

    // scores over own T half
    const uint2* uep = (const uint2*)(g_Ueh + (size_t)b * NT * NH);
    float m = -1e30f;
    for (int tt = 0; tt < 84; tt += 4) {
        float s[4];
        #pragma unroll
        for (int j = 0; j < 4; j++) {
            uint2 raw = uep[(tbeg + tt + j) * 32 + lane];
            float2 f0 = __half22float2(*(__half2*)&raw.x);
            float2 f1 = __half22float2(*(__half2*)&raw.y);
            s[j] = ftanh_fast(f0.x + q4.x) * v4.x + ftanh_fast(f0.y + q4.y) * v4.y
                 + ftanh_fast(f1.x + q4.z) * v4.z + ftanh_fast(f1.y + q4.w) * v4.w;
        }
        #pragma unroll
        for (int j = 0; j < 4; j++) {
            #pragma unroll
            for (int o = 16; o > 0; o >>= 1) s[j] += __shfl_xor_sync(0xffffffffu, s[j], o);
            m = fmaxf(m, s[j]);
        }
        if (lane == 0) {
            ssh[row][tbeg + tt] = s[0]; ssh[row][tbeg + tt + 1] = s[1];
            ssh[row][tbeg + tt + 2] = s[2]; ssh[row][tbeg + tt + 3] = s[3];
        }
    }
    if (lane == 0) mred[row][hf] = m;
    __syncthreads();
    m = fmaxf(mred[row][0], mred[row][1]);

    // softmax weights over own half
    float Z = 0.f;
    for (int t = tbeg + lane; t < tbeg + 84; t += 32) {
        float w = __expf(ssh[row][t] - m);
        ssh[row][t] = w;
        Z += w;
    }
    #pragma unroll
    for (int o = 16; o > 0; o >>= 1) Z += __shfl_xor_sync(0xffffffffu, Z, o);
    if (lane == 0) zred[row][hf] = Z;
    __syncthreads();
    float invZ = __fdividef(1.f, zred[row][0] + zred[row][1]);

    // partial context over own half
    const uint2* ep = (const uint2*)(g_ench + (size_t)b * NT * NH);
    float4 ca = {0.f, 0.f, 0.f, 0.f};
    for (int tt = 0; tt < 84; tt += 4) {
        #pragma unroll
        for (int j = 0; j < 4; j++) {
            float w = ssh[row][tbeg + tt + j];
            uint2 raw = ep[(tbeg + tt + j) * 32 + lane];
            float2 f0 = __half22float2(*(__half2*)&raw.x);
            float2 f1 = __half22float2(*(__half2*)&raw.y);
            ca.x += w * f0.x; ca.y += w * f0.y;
            ca.z += w * f1.x; ca.w += w * f1.y;
        }
    }
    if (hf == 1) *(float4*)&cpart[row][lane * 4] = ca;
    __syncthreads();
    if (hf == 0) {
        float4 p = *(float4*)&cpart[row][lane * 4];
        ca.x = (ca.x + p.x) * invZ; ca.y = (ca.y + p.y) * invZ;
        ca.z = (ca.z + p.z) * invZ; ca.w = (ca.w + p.w) * invZ;
        *(float4*)&g_ctx[b * NH + lane * 4] = ca;
    }
}

// ------------------------- decoder LSTM cell + fc (per step) -------------------------
__global__ void __launch_bounds__(256) cell_kernel(const float* __restrict__ x,
                                                   const float* __restrict__ decWih,
                                                   const float* __restrict__ fcW,
                                                   const float* __restrict__ fcb,
                                                   float* __restrict__ out, int step)
{
    __shared__ float ch[16][2 * NH];
    __shared__ float din[16];
    int tid = threadIdx.x;
    int b0 = blockIdx.x * 16;
    for (int i = tid; i < 16 * NH; i += 256) {
        int r = i >> 7, k = i & 127;
        ch[r][k]      = g_ctx[(b0 + r) * NH + k];
        ch[r][NH + k] = g_h  [(b0 + r) * NH + k];
    }
    if (tid < 16) din[tid] = (step == 0) ? x[(b0 + tid) * NT + (NT - 1)] : g_pred[b0 + tid];
    __syncthreads();

    int u = tid & 127, rh = tid >> 7;
    float w0[4], bs[4];
    #pragma unroll
    for (int j = 0; j < 4; j++) {
        w0[j] = decWih[(u + 128 * j) * (NH + 1)];
        bs[j] = g_decB[u + 128 * j];
    }
    float acc[4][8];
    #pragma unroll
    for (int r = 0; r < 8; r++) {
        float dv = din[rh * 8 + r];
        #pragma unroll
        for (int j = 0; j < 4; j++) acc[j][r] = dv * w0[j] + bs[j];
    }
    #pragma unroll 2
    for (int k = 0; k < 2 * NH; k++) {
        float w0_ = g_WdT[k * NG + u];
        float w1_ = g_WdT[k * NG + u + 128];
        float w2_ = g_WdT[k * NG + u + 256];
        float w3_ = g_WdT[k * NG + u + 384];
        #pragma unroll
        for (int r = 0; r < 8; r++) {
            float hv = ch[rh * 8 + r][k];
            acc[0][r] += w0_ * hv; acc[1][r] += w1_ * hv;
            acc[2][r] += w2_ * hv; acc[3][r] += w3_ * hv;
        }
    }
    float hnew[8];
    #pragma unroll
    for (int r = 0; r < 8; r++) {
        int b = b0 + rh * 8 + r;
        float cold = g_c[b * NH + u];
        float iv = fsig(acc[0][r]), fv = fsig(acc[1][r]);
        float gv = ftanh_(acc[2][r]), ov = fsig(acc[3][r]);
        float cn = fv * cold + iv * gv;
        float hn = ov * ftanh_(cn);
        g_c[b * NH + u] = cn;
        g_h[b * NH + u] = hn;
        hnew[r] = hn;
    }
    __syncthreads();
    #pragma unroll
    for (int r = 0; r < 8; r++) ch[rh * 8 + r][u] = hnew[r];
    __syncthreads();

    int wid = tid >> 5, lane = tid & 31;
    float fw0 = fcW[lane], fw1 = fcW[lane + 32], fw2 = fcW[lane + 64], fw3 = fcW[lane + 96];
    #pragma unroll
    for (int rr = 0; rr < 2; rr++) {
        int r = wid * 2 + rr;
        float s = ch[r][lane] * fw0 + ch[r][lane + 32] * fw1
                + ch[r][lane + 64] * fw2 + ch[r][lane + 96] * fw3;
        #pragma unroll
        for (int off = 16; off > 0; off >>= 1) s += __shfl_xor_sync(0xffffffffu, s, off);
        if (lane == 0) {
            float p = s + fcb[0];
            out[(b0 + r) * NO + step] = p;
            g_pred[b0 + r] = p;
        }
    }
}

// ------------------------- launch -------------------------
extern "C" void kernel_launch(void* const* d_in, const int* in_sizes, int n_in,
                              void* d_out, int out_size)
{
    const float* x      = (const float*)d_in[0];
    const float* encWih = (const float*)d_in[1];
    const float* encWhh = (const float*)d_in[2];
    const float* encBih = (const float*)d_in[3];
    const float* encBhh = (const float*)d_in[4];
    const float* Wa     = (const float*)d_in[5];
    const float* Ua     = (const float*)d_in[6];
    const float* va     = (const float*)d_in[7];
    const float* decWih = (const float*)d_in[8];
    const float* decWhh = (const float*)d_in[9];
    const float* decBih = (const float*)d_in[10];
    const float* decBhh = (const float*)d_in[11];
    const float* fcW    = (const float*)d_in[12];
    const float* fcb    = (const float*)d_in[13];
    float* out = (float*)d_out;

    pack_kernel<<<256, 256>>>(encWih, encWhh, encBih, encBhh, Wa, Ua,
                              decWih, decWhh, decBih, decBhh);
    enc_kernel<<<NB / 32, 256>>>(x);
    ue_kernel<<<NB * NT / 32, 256>>>();
    for (int d = 0; d < NO; d++) {
        att_kernel<<<NB / 4, 256>>>(va);
        cell_kernel<<<NB / 16, 256>>>(x, decWih, fcW, fcb, out, d);
    }
}

// round 5
// speedup vs baseline: 3.0201x; 1.3580x over previous
#include <cuda_runtime.h>
#include <cuda_fp16.h>
#include <cstdint>

#define NB 4096
#define NT 168
#define NH 128
#define NG 512
#define NO 24

// ------------------------- device scratch -------------------------
__device__ __half g_ench[NB * NT * NH];  // encoder hidden states (B*T, H) fp16
__device__ __half g_Ueh [NB * NT * NH];  // Ua @ enc_outs        (B*T, H) fp16
__device__ float g_h  [NB * NH];
__device__ float g_c  [NB * NH];
__device__ float g_ctx[NB * NH];
__device__ float g_pred[NB];
__device__ __half g_WencP[8 * 8 * 8 * 32 * 4];  // enc Whh B-frags [wid][kt][j][lane][4]
__device__ __half g_UaP  [16 * 8 * 32 * 4];     // Ua B-frags [nt][kt][lane][4]
__device__ __half g_WdP  [8 * 16 * 8 * 32 * 4]; // dec [Wih(ctx)|Whh] B-frags, K=256
__device__ float g_encBp[NG];           // enc bias, n = u*4+gate
__device__ float g_wihp [NG];           // enc Wih,  n = u*4+gate
__device__ float g_decBp[NG];           // dec bias, n = u*4+gate
__device__ float g_dinW [NG];           // dec Wih col 0 (din), n = u*4+gate
__device__ float g_WaT [NH * NH];       // Wa transposed: [k][u]

// accurate activations (recurrent paths)
__device__ __forceinline__ float fsig(float x)   { return __fdividef(1.f, 1.f + __expf(-x)); }
__device__ __forceinline__ float ftanh_(float x) { return 1.f - __fdividef(2.f, 1.f + __expf(2.f * x)); }
// fast tanh (attention energy only, non-recurrent)
__device__ __forceinline__ float ftanh_fast(float x) { asm("tanh.approx.f32 %0, %0;" : "+f"(x)); return x; }

// ------------------------- mma helpers -------------------------
__device__ __forceinline__ void ldmA(uint32_t a[4], const __half* p) {
    uint32_t addr = (uint32_t)__cvta_generic_to_shared(p);
    asm volatile("ldmatrix.sync.aligned.m8n8.x4.shared.b16 {%0,%1,%2,%3}, [%4];"
        : "=r"(a[0]), "=r"(a[1]), "=r"(a[2]), "=r"(a[3]) : "r"(addr));
}
__device__ __forceinline__ void mma16816(float c[4], const uint32_t a[4], uint2 b) {
    asm volatile("mma.sync.aligned.m16n8k16.row.col.f32.f16.f16.f32 "
        "{%0,%1,%2,%3},{%4,%5,%6,%7},{%8,%9},{%0,%1,%2,%3};"
        : "+f"(c[0]), "+f"(c[1]), "+f"(c[2]), "+f"(c[3])
        : "r"(a[0]), "r"(a[1]), "r"(a[2]), "r"(a[3]), "r"(b.x), "r"(b.y));
}

// ------------------------- weight packing -------------------------
__global__ void pack_kernel(const float* __restrict__ encWih,
                            const float* __restrict__ encWhh,
                            const float* __restrict__ encBih, const float* __restrict__ encBhh,
                            const float* __restrict__ Wa, const float* __restrict__ Ua,
                            const float* __restrict__ decWih, const float* __restrict__ decWhh,
                            const float* __restrict__ decBih, const float* __restrict__ decBhh)
{
    int stride = gridDim.x * blockDim.x;
    int i0 = blockIdx.x * blockDim.x + threadIdx.x;

    // enc Whh fragments: n = u*4 + gate, K=128
    for (int idx = i0; idx < 8 * 8 * 8 * 32 * 4; idx += stride) {
        int q = idx & 3, lane = (idx >> 2) & 31;
        int rest = idx >> 7;
        int j = rest & 7, kt = (rest >> 3) & 7, wid = rest >> 6;
        int g = lane >> 2, tg = lane & 3;
        int n = wid * 64 + j * 8 + g;
        int u = n >> 2, gate = n & 3;
        int k = kt * 16 + ((q < 2) ? (tg * 2 + q) : (tg * 2 + 8 + (q - 2)));
        g_WencP[idx] = __float2half_rn(encWhh[(gate * 128 + u) * NH + k]);
    }
    // dec [ctx|h] fragments: n = u*4 + gate, K=256
    for (int idx = i0; idx < 8 * 16 * 8 * 32 * 4; idx += stride) {
        int q = idx & 3, lane = (idx >> 2) & 31;
        int rest = idx >> 7;
        int j = rest & 7, kt = (rest >> 3) & 15, wid = rest >> 7;
        int g = lane >> 2, tg = lane & 3;
        int n = wid * 64 + j * 8 + g;
        int u = n >> 2, gate = n & 3;
        int k = kt * 16 + ((q < 2) ? (tg * 2 + q) : (tg * 2 + 8 + (q - 2)));
        float v = (k < NH) ? decWih[(gate * 128 + u) * (NH + 1) + 1 + k]
                           : decWhh[(gate * 128 + u) * NH + (k - NH)];
        g_WdP[idx] = __float2half_rn(v);
    }
    // Ua fragments: n = unit
    for (int idx = i0; idx < 16 * 8 * 32 * 4; idx += stride) {
        int q = idx & 3, lane = (idx >> 2) & 31;
        int rest = idx >> 7;
        int kt = rest & 7, nt = rest >> 3;
        int g = lane >> 2, tg = lane & 3;
        int n = nt * 8 + g;
        int k = kt * 16 + ((q < 2) ? (tg * 2 + q) : (tg * 2 + 8 + (q - 2)));
        g_UaP[idx] = __float2half_rn(Ua[n * NH + k]);
    }
    for (int i = i0; i < NH * NH; i += stride) {
        int k = i / NH, u = i % NH;
        g_WaT[i] = Wa[u * NH + k];
    }
    for (int i = i0; i < NG; i += stride) {
        int u = i >> 2, gate = i & 3;
        g_encBp[i] = encBih[gate * 128 + u] + encBhh[gate * 128 + u];
        g_wihp[i]  = encWih[gate * 128 + u];
        g_decBp[i] = decBih[gate * 128 + u] + decBhh[gate * 128 + u];
        g_dinW[i]  = decWih[(gate * 128 + u) * (NH + 1)];
    }
}

// ------------------------- encoder (HMMA, one launch, 168 steps) -------------------------
__global__ void __launch_bounds__(256) enc_kernel(const float* __restrict__ x)
{
    __shared__ __half hsh[32][136];
    __shared__ float biassh[NG], wihsh[NG];
    int tid = threadIdx.x;
    int wid = tid >> 5, lane = tid & 31;
    int b0 = blockIdx.x * 32;
    int g = lane >> 2, tg = lane & 3, tg2 = tg >> 1;
    int odd = tg & 1;
    int lrow = lane & 15;
    int lcol = (lane >> 4) << 3;

    for (int i = tid; i < NG; i += 256) { biassh[i] = g_encBp[i]; wihsh[i] = g_wihp[i]; }
    for (int i = tid; i < 32 * 136; i += 256) ((__half*)hsh)[i] = __ushort_as_half(0);

    float cst[16];
    #pragma unroll
    for (int i = 0; i < 16; i++) cst[i] = 0.f;

    const uint2* wbase = ((const uint2*)g_WencP) + wid * 2048 + lane;
    __syncthreads();

    for (int t = 0; t < NT; t++) {
        float xv[2];
        #pragma unroll
        for (int mi = 0; mi < 2; mi++)
            xv[mi] = x[(b0 + mi * 16 + g + (odd ? 8 : 0)) * NT + t];

        float acc[2][8][4];
        #pragma unroll
        for (int mi = 0; mi < 2; mi++)
            #pragma unroll
            for (int j = 0; j < 8; j++)
                #pragma unroll
                for (int q = 0; q < 4; q++) acc[mi][j][q] = 0.f;

        #pragma unroll
        for (int kt = 0; kt < 8; kt++) {
            uint32_t a[2][4];
            #pragma unroll
            for (int mi = 0; mi < 2; mi++)
                ldmA(a[mi], &hsh[mi * 16 + lrow][kt * 16 + lcol]);
            #pragma unroll
            for (int j = 0; j < 8; j++) {
                uint2 b = wbase[(kt * 8 + j) * 32];
                mma16816(acc[0][j], a[0], b);
                mma16816(acc[1][j], a[1], b);
            }
        }
        __syncthreads();

        #pragma unroll
        for (int mi = 0; mi < 2; mi++) {
            int row = mi * 16 + g + (odd ? 8 : 0);
            #pragma unroll
            for (int j = 0; j < 8; j++) {
                float t0 = __shfl_xor_sync(0xffffffffu, acc[mi][j][0], 1);
                float t1 = __shfl_xor_sync(0xffffffffu, acc[mi][j][1], 1);
                float t2 = __shfl_xor_sync(0xffffffffu, acc[mi][j][2], 1);
                float t3 = __shfl_xor_sync(0xffffffffu, acc[mi][j][3], 1);
                float gi, gf, gg, go;
                if (!odd) { gi = acc[mi][j][0]; gf = acc[mi][j][1]; gg = t0; go = t1; }
                else      { gi = t2; gf = t3; gg = acc[mi][j][2]; go = acc[mi][j][3]; }
                int u = wid * 16 + j * 2 + tg2;
                float4 bi = *(const float4*)&biassh[u * 4];
                float4 wi = *(const float4*)&wihsh[u * 4];
                gi += bi.x + xv[mi] * wi.x;
                gf += bi.y + xv[mi] * wi.y;
                gg += bi.z + xv[mi] * wi.z;
                go += bi.w + xv[mi] * wi.w;
                float c = fsig(gf) * cst[mi * 8 + j] + fsig(gi) * ftanh_(gg);
                cst[mi * 8 + j] = c;
                float h = fsig(go) * ftanh_(c);
                hsh[row][u] = __float2half_rn(h);
            }
        }
        __syncthreads();

        for (int i = tid; i < 512; i += 256) {
            int r = i >> 4, ch = i & 15;
            uint4 v = *(uint4*)&hsh[r][ch * 8];
            *(uint4*)&g_ench[(size_t)(b0 + r) * (NT * NH) + (size_t)t * NH + ch * 8] = v;
        }
    }
    __syncthreads();
    for (int i = tid; i < 32 * NH; i += 256) {
        int r = i >> 7, u2 = i & 127;
        g_h[(b0 + r) * NH + u2] = __half2float(hsh[r][u2]);
    }
    #pragma unroll
    for (int mi = 0; mi < 2; mi++) {
        int row = mi * 16 + g + (odd ? 8 : 0);
        #pragma unroll
        for (int j = 0; j < 8; j++) {
            int u = wid * 16 + j * 2 + tg2;
            g_c[(b0 + row) * NH + u] = cst[mi * 8 + j];
        }
    }
}

// ------------------------- Ue = enc_outs @ Ua^T (HMMA) -------------------------
__global__ void __launch_bounds__(256) ue_kernel()
{
    __shared__ __half ash[32][136];
    int tid = threadIdx.x;
    int wid = tid >> 5, lane = tid & 31;
    size_t row0 = (size_t)blockIdx.x * 32;

    for (int i = tid; i < 512; i += 256) {
        int r = i >> 4, ch = i & 15;
        *(uint4*)&ash[r][ch * 8] = *(const uint4*)&g_ench[(row0 + r) * NH + ch * 8];
    }
    __syncthreads();

    int mi = wid & 1, nw = wid >> 1;
    int lrow = lane & 15, lcol = (lane >> 4) << 3;
    float acc[4][4];
    #pragma unroll
    for (int nt = 0; nt < 4; nt++)
        #pragma unroll
        for (int q = 0; q < 4; q++) acc[nt][q] = 0.f;

    const uint2* ub = (const uint2*)g_UaP;
    #pragma unroll
    for (int kt = 0; kt < 8; kt++) {
        uint32_t a[4];
        ldmA(a, &ash[mi * 16 + lrow][kt * 16 + lcol]);
        #pragma unroll
        for (int nt = 0; nt < 4; nt++) {
            int ntg = nw * 4 + nt;
            uint2 b = ub[(ntg * 8 + kt) * 32 + lane];
            mma16816(acc[nt], a, b);
        }
    }
    __syncthreads();

    int g = lane >> 2, tg = lane & 3;
    #pragma unroll
    for (int nt = 0; nt < 4; nt++) {
        int n = (nw * 4 + nt) * 8 + tg * 2;
        *(__half2*)&ash[mi * 16 + g][n]     = __floats2half2_rn(acc[nt][0], acc[nt][1]);
        *(__half2*)&ash[mi * 16 + 8 + g][n] = __floats2half2_rn(acc[nt][2], acc[nt][3]);
    }
    __syncthreads();
    for (int i = tid; i < 512; i += 256) {
        int r = i >> 4, ch = i & 15;
        *(uint4*)&g_Ueh[(row0 + r) * NH + ch * 8] = *(uint4*)&ash[r][ch * 8];
    }
}

// ------------------------- decoder attention (per step, fused single pass) -------------------------
// block: 256 thr = 8 warps; warp = one batch row. Lanes 0-15 handle even t, 16-31 odd t.
// No max subtraction: |score| <= ||va||_1 ~ 9.2, exp() safe in fp32.
__global__ void __launch_bounds__(256) att_kernel(const float* __restrict__ va)
{
    __shared__ float hsh[8][NH];
    __shared__ float qsh[8][NH];
    int tid = threadIdx.x;
    int b0 = blockIdx.x * 8;
    for (int i = tid; i < 8 * NH; i += 256) hsh[i >> 7][i & 127] = g_h[b0 * NH + i];
    __syncthreads();

    // q = h @ Wa^T : thread (u, rh) covers 4 rows
    {
        int u = tid & 127, rh = tid >> 7;
        float qa[4] = {0.f, 0.f, 0.f, 0.f};
        #pragma unroll 4
        for (int k = 0; k < NH; k++) {
            float w = g_WaT[k * NH + u];
            #pragma unroll
            for (int r = 0; r < 4; r++) qa[r] += w * hsh[rh * 4 + r][k];
        }
        #pragma unroll
        for (int r = 0; r < 4; r++) qsh[rh * 4 + r][u] = qa[r];
    }
    __syncthreads();

    int wid = tid >> 5, lane = tid & 31;
    int sub = lane & 15;
    int b = b0 + wid;

    float4 qa = *(float4*)&qsh[wid][sub * 8];
    float4 qb = *(float4*)&qsh[wid][sub * 8 + 4];
    float4 va0 = *(const float4*)&va[sub * 8];
    float4 va1 = *(const float4*)&va[sub * 8 + 4];

    const uint4* uep = (const uint4*)(g_Ueh + (size_t)b * NT * NH);
    const uint4* ep  = (const uint4*)(g_ench + (size_t)b * NT * NH);

    float ca[8];
    #pragma unroll
    for (int j = 0; j < 8; j++) ca[j] = 0.f;
    float Z = 0.f;

    #pragma unroll 2
    for (int i = 0; i < NT / 2; i++) {
        uint4 ue = uep[i * 32 + lane];
        uint4 en = ep[i * 32 + lane];
        float2 e0 = __half22float2(*(__half2*)&ue.x);
        float2 e1 = __half22float2(*(__half2*)&ue.y);
        float2 e2 = __half22float2(*(__half2*)&ue.z);
        float2 e3 = __half22float2(*(__half2*)&ue.w);
        float s = ftanh_fast(e0.x + qa.x) * va0.x + ftanh_fast(e0.y + qa.y) * va0.y
                + ftanh_fast(e1.x + qa.z) * va0.z + ftanh_fast(e1.y + qa.w) * va0.w
                + ftanh_fast(e2.x + qb.x) * va1.x + ftanh_fast(e2.y + qb.y) * va1.y
                + ftanh_fast(e3.x + qb.z) * va1.z + ftanh_fast(e3.y + qb.w) * va1.w;
        s += __shfl_xor_sync(0xffffffffu, s, 8);
        s += __shfl_xor_sync(0xffffffffu, s, 4);
        s += __shfl_xor_sync(0xffffffffu, s, 2);
        s += __shfl_xor_sync(0xffffffffu, s, 1);
        float w = __expf(s);
        Z += w;
        float2 n0 = __half22float2(*(__half2*)&en.x);
        float2 n1 = __half22float2(*(__half2*)&en.y);
        float2 n2 = __half22float2(*(__half2*)&en.z);
        float2 n3 = __half22float2(*(__half2*)&en.w);
        ca[0] += w * n0.x; ca[1] += w * n0.y;
        ca[2] += w * n1.x; ca[3] += w * n1.y;
        ca[4] += w * n2.x; ca[5] += w * n2.y;
        ca[6] += w * n3.x; ca[7] += w * n3.y;
    }
    // merge halves (even-t lane j pairs with odd-t lane j+16 covering same h slice)
    Z += __shfl_xor_sync(0xffffffffu, Z, 16);
    #pragma unroll
    for (int j = 0; j < 8; j++) ca[j] += __shfl_xor_sync(0xffffffffu, ca[j], 16);
    float invZ = __fdividef(1.f, Z);
    if (lane < 16) {
        float4 o0 = {ca[0] * invZ, ca[1] * invZ, ca[2] * invZ, ca[3] * invZ};
        float4 o1 = {ca[4] * invZ, ca[5] * invZ, ca[6] * invZ, ca[7] * invZ};
        *(float4*)&g_ctx[b * NH + sub * 8]     = o0;
        *(float4*)&g_ctx[b * NH + sub * 8 + 4] = o1;
    }
}

// ------------------------- decoder LSTM cell + fc (HMMA, per step) -------------------------
// block: 256 thr = 8 warps, 32 rows. K=256 over fp16 [ctx|h]; din + bias in epilogue.
__global__ void __launch_bounds__(256) cell_kernel(const float* __restrict__ x,
                                                   const float* __restrict__ fcW,
                                                   const float* __restrict__ fcb,
                                                   float* __restrict__ out, int step)
{
    __shared__ __half ash[32][264];
    __shared__ float biassh[NG], dinwsh[NG];
    __shared__ float dinsh[32];
    __shared__ float hout[32][NH];
    int tid = threadIdx.x;
    int wid = tid >> 5, lane = tid & 31;
    int b0 = blockIdx.x * 32;
    int g = lane >> 2, tg = lane & 3, tg2 = tg >> 1;
    int odd = tg & 1;
    int lrow = lane & 15;
    int lcol = (lane >> 4) << 3;

    for (int i = tid; i < NG; i += 256) { biassh[i] = g_decBp[i]; dinwsh[i] = g_dinW[i]; }
    // stage ctx|h as fp16
    for (int i = tid; i < 32 * 64; i += 256) {
        int r = i >> 6, k2 = i & 63;
        float2 cv = ((const float2*)g_ctx)[(size_t)(b0 + r) * 64 + k2];
        float2 hv = ((const float2*)g_h)  [(size_t)(b0 + r) * 64 + k2];
        *(__half2*)&ash[r][k2 * 2]       = __floats2half2_rn(cv.x, cv.y);
        *(__half2*)&ash[r][128 + k2 * 2] = __floats2half2_rn(hv.x, hv.y);
    }
    if (tid < 32) dinsh[tid] = (step == 0) ? x[(b0 + tid) * NT + (NT - 1)] : g_pred[b0 + tid];
    __syncthreads();

    float acc[2][8][4];
    #pragma unroll
    for (int mi = 0; mi < 2; mi++)
        #pragma unroll
        for (int j = 0; j < 8; j++)
            #pragma unroll
            for (int q = 0; q < 4; q++) acc[mi][j][q] = 0.f;

    const uint2* wbase = ((const uint2*)g_WdP) + wid * 4096 + lane;
    #pragma unroll
    for (int kt = 0; kt < 16; kt++) {
        uint32_t a[2][4];
        #pragma unroll
        for (int mi = 0; mi < 2; mi++)
            ldmA(a[mi], &ash[mi * 16 + lrow][kt * 16 + lcol]);
        #pragma unroll
        for (int j = 0; j < 8; j++) {
            uint2 b = wbase[(kt * 8 + j) * 32];
            mma16816(acc[0][j], a[0], b);
            mma16816(acc[1][j], a[1], b);
        }
    }

    #pragma unroll
    for (int mi = 0; mi < 2; mi++) {
        int row = mi * 16 + g + (odd ? 8 : 0);
        float dv = dinsh[row];
        #pragma unroll
        for (int j = 0; j < 8; j++) {
            float t0 = __shfl_xor_sync(0xffffffffu, acc[mi][j][0], 1);
            float t1 = __shfl_xor_sync(0xffffffffu, acc[mi][j][1], 1);
            float t2 = __shfl_xor_sync(0xffffffffu, acc[mi][j][2], 1);
            float t3 = __shfl_xor_sync(0xffffffffu, acc[mi][j][3], 1);
            float gi, gf, gg, go;
            if (!odd) { gi = acc[mi][j][0]; gf = acc[mi][j][1]; gg = t0; go = t1; }
            else      { gi = t2; gf = t3; gg = acc[mi][j][2]; go = acc[mi][j][3]; }
            int u = wid * 16 + j * 2 + tg2;
            float4 bi = *(const float4*)&biassh[u * 4];
            float4 wi = *(const float4*)&dinwsh[u * 4];
            gi += bi.x + dv * wi.x;
            gf += bi.y + dv * wi.y;
            gg += bi.z + dv * wi.z;
            go += bi.w + dv * wi.w;
            int b = b0 + row;
            float cold = g_c[b * NH + u];
            float cn = fsig(gf) * cold + fsig(gi) * ftanh_(gg);
            float hn = fsig(go) * ftanh_(cn);
            g_c[b * NH + u] = cn;
            g_h[b * NH + u] = hn;
            hout[row][u] = hn;
        }
    }
    __syncthreads();

    // pred = h2 @ fcW^T + fcb ; warp handles 4 rows
    float fw0 = fcW[lane], fw1 = fcW[lane + 32], fw2 = fcW[lane + 64], fw3 = fcW[lane + 96];
    #pragma unroll
    for (int rr = 0; rr < 4; rr++) {
        int r = wid * 4 + rr;
        float s = hout[r][lane] * fw0 + hout[r][lane + 32] * fw1
                + hout[r][lane + 64] * fw2 + hout[r][lane + 96] * fw3;
        #pragma unroll
        for (int off = 16; off > 0; off >>= 1) s += __shfl_xor_sync(0xffffffffu, s, off);
        if (lane == 0) {
            float p = s + fcb[0];
            out[(b0 + r) * NO + step] = p;
            g_pred[b0 + r] = p;
        }
    }
}

// ------------------------- launch -------------------------
extern "C" void kernel_launch(void* const* d_in, const int* in_sizes, int n_in,
                              void* d_out, int out_size)
{
    const float* x      = (const float*)d_in[0];
    const float* encWih = (const float*)d_in[1];
    const float* encWhh = (const float*)d_in[2];
    const float* encBih = (const float*)d_in[3];
    const float* encBhh = (const float*)d_in[4];
    const float* Wa     = (const float*)d_in[5];
    const float* Ua     = (const float*)d_in[6];
    const float* va     = (const float*)d_in[7];
    const float* decWih = (const float*)d_in[8];
    const float* decWhh = (const float*)d_in[9];
    const float* decBih = (const float*)d_in[10];
    const float* decBhh = (const float*)d_in[11];
    const float* fcW    = (const float*)d_in[12];
    const float* fcb    = (const float*)d_in[13];
    float* out = (float*)d_out;

    pack_kernel<<<256, 256>>>(encWih, encWhh, encBih, encBhh, Wa, Ua,
                              decWih, decWhh, decBih, decBhh);
    enc_kernel<<<NB / 32, 256>>>(x);
    ue_kernel<<<NB * NT / 32, 256>>>();
    for (int d = 0; d < NO; d++) {
        att_kernel<<<NB / 8, 256>>>(va);
        cell_kernel<<<NB / 32, 256>>>(x, fcW, fcb, out, d);
    }
}